// round 6
// baseline (speedup 1.0000x reference)
#include <cuda_runtime.h>
#include <stdint.h>

#define NN   100000
#define INC  1024
#define HIDD 128
#define NE   1600000

// -------- scratch (device globals; no allocations allowed) --------
__device__ float g_hs[(size_t)NN * HIDD];   // h * dinv  (51.2 MB)
__device__ float g_dinv[NN];
__device__ int   g_cnt[NN];
__device__ int   g_start[NN + 1];
__device__ int   g_cursor[NN];
__device__ int   g_srcbuf[NE];

// -------- init: zero counters --------
__global__ void init_kernel() {
    int i = blockIdx.x * blockDim.x + threadIdx.x;
    if (i < NN) { g_cnt[i] = 0; g_cursor[i] = 0; }
}

// -------- count in-degrees (destinations = edge_index[1]) --------
__global__ void count_kernel(const int* __restrict__ ei) {
    int e = blockIdx.x * blockDim.x + threadIdx.x;
    if (e < NE) {
        int c = ei[NE + e];
        if ((unsigned)c < NN) atomicAdd(&g_cnt[c], 1);
    }
}

// -------- dinv = rsqrt(deg + 1)  (self-loop included) --------
__global__ void dinv_kernel() {
    int i = blockIdx.x * blockDim.x + threadIdx.x;
    if (i < NN) g_dinv[i] = rsqrtf((float)g_cnt[i] + 1.0f);
}

// -------- single-block exclusive scan over g_cnt -> g_start --------
__global__ void scan_kernel() {
    __shared__ int warpsums[32];
    __shared__ int s_carry;
    const int CH = 1024;
    int tid = threadIdx.x, lane = tid & 31, wid = tid >> 5;
    if (tid == 0) { s_carry = 0; g_start[0] = 0; }
    __syncthreads();
    int nch = (NN + CH - 1) / CH;
    for (int c = 0; c < nch; c++) {
        int i = c * CH + tid;
        int v = (i < NN) ? g_cnt[i] : 0;
        int x = v;
        #pragma unroll
        for (int off = 1; off < 32; off <<= 1) {
            int y = __shfl_up_sync(0xffffffff, x, off);
            if (lane >= off) x += y;
        }
        if (lane == 31) warpsums[wid] = x;
        __syncthreads();
        if (wid == 0) {
            int w = warpsums[lane];
            #pragma unroll
            for (int off = 1; off < 32; off <<= 1) {
                int y = __shfl_up_sync(0xffffffff, w, off);
                if (lane >= off) w += y;
            }
            warpsums[lane] = w;
        }
        __syncthreads();
        int incl = x + (wid > 0 ? warpsums[wid - 1] : 0) + s_carry;
        if (i < NN) g_start[i + 1] = incl;
        __syncthreads();
        if (tid == CH - 1) s_carry = incl;
        __syncthreads();
    }
}

// -------- fill CSR buckets with source ids --------
__global__ void fill_kernel(const int* __restrict__ ei) {
    int e = blockIdx.x * blockDim.x + threadIdx.x;
    if (e < NE) {
        int r = ei[e];
        int c = ei[NE + e];
        if ((unsigned)c < NN && (unsigned)r < NN) {
            int pos = atomicAdd(&g_cursor[c], 1);
            g_srcbuf[g_start[c] + pos] = r;
        }
    }
}

// -------- GEMM: hs = (X @ W) * dinv[row]  (BM=128,BN=128,BK=16, 256 thr) --------
__global__ __launch_bounds__(256, 2)
void gemm_kernel(const float* __restrict__ X, const float* __restrict__ W) {
    __shared__ float As[16][129];   // transposed, padded (conflict-free)
    __shared__ float Bs[16][128];
    int tid = threadIdx.x;
    int tx = tid & 15, ty = tid >> 4;
    int bm = blockIdx.x * 128;
    float acc[8][8];
    #pragma unroll
    for (int i = 0; i < 8; i++)
        #pragma unroll
        for (int j = 0; j < 8; j++) acc[i][j] = 0.0f;

    for (int k0 = 0; k0 < INC; k0 += 16) {
        // A tile: 128 rows x 16 cols = 512 float4, 2 per thread
        #pragma unroll
        for (int i = 0; i < 2; i++) {
            int id  = tid + i * 256;
            int row = id >> 2;
            int cv  = (id & 3) * 4;
            float4 a = make_float4(0.f, 0.f, 0.f, 0.f);
            if (bm + row < NN)
                a = *(const float4*)(X + (size_t)(bm + row) * INC + k0 + cv);
            As[cv + 0][row] = a.x; As[cv + 1][row] = a.y;
            As[cv + 2][row] = a.z; As[cv + 3][row] = a.w;
        }
        // B tile: 16 rows x 128 cols = 512 float4, 2 per thread
        #pragma unroll
        for (int i = 0; i < 2; i++) {
            int id  = tid + i * 256;
            int row = id >> 5;
            int cv  = (id & 31) * 4;
            *(float4*)&Bs[row][cv] =
                *(const float4*)(W + (size_t)(k0 + row) * HIDD + cv);
        }
        __syncthreads();
        #pragma unroll
        for (int k = 0; k < 16; k++) {
            float ra[8], rb[8];
            #pragma unroll
            for (int i = 0; i < 8; i++) ra[i] = As[k][ty * 8 + i];
            #pragma unroll
            for (int j = 0; j < 8; j++) rb[j] = Bs[k][tx * 8 + j];
            #pragma unroll
            for (int i = 0; i < 8; i++)
                #pragma unroll
                for (int j = 0; j < 8; j++)
                    acc[i][j] = fmaf(ra[i], rb[j], acc[i][j]);
        }
        __syncthreads();
    }
    // epilogue: hs = h * dinv[row]
    #pragma unroll
    for (int i = 0; i < 8; i++) {
        int row = bm + ty * 8 + i;
        if (row < NN) {
            float d = g_dinv[row];
            #pragma unroll
            for (int j = 0; j < 8; j += 4) {
                float4 v;
                v.x = acc[i][j + 0] * d;
                v.y = acc[i][j + 1] * d;
                v.z = acc[i][j + 2] * d;
                v.w = acc[i][j + 3] * d;
                *(float4*)(g_hs + (size_t)row * HIDD + tx * 8 + j) = v;
            }
        }
    }
}

// -------- gather-reduce: one warp per destination node --------
__global__ void gather_kernel(float* __restrict__ out) {
    int gw = (blockIdx.x * blockDim.x + threadIdx.x) >> 5;
    int lane = threadIdx.x & 31;
    if (gw >= NN) return;
    const float4* hs4 = (const float4*)g_hs;
    int s0 = g_start[gw], s1 = g_start[gw + 1];
    // self-loop term (hs already carries dinv[src])
    float4 acc = hs4[(size_t)gw * 32 + lane];
    for (int j = s0; j < s1; j++) {
        int src = g_srcbuf[j];
        float4 v = hs4[(size_t)src * 32 + lane];
        acc.x += v.x; acc.y += v.y; acc.z += v.z; acc.w += v.w;
    }
    float d = g_dinv[gw];
    float4 r = make_float4(acc.x * d, acc.y * d, acc.z * d, acc.w * d);
    ((float4*)out)[(size_t)gw * 32 + lane] = r;
}

extern "C" void kernel_launch(void* const* d_in, const int* in_sizes, int n_in,
                              void* d_out, int out_size) {
    const float* X  = (const float*)d_in[0];
    const float* W  = (const float*)d_in[1];
    const int*   ei = (const int*)d_in[2];
    float* out = (float*)d_out;

    init_kernel <<<(NN + 255) / 256, 256>>>();
    count_kernel<<<(NE + 255) / 256, 256>>>(ei);
    dinv_kernel <<<(NN + 255) / 256, 256>>>();
    scan_kernel <<<1, 1024>>>();
    fill_kernel <<<(NE + 255) / 256, 256>>>(ei);
    gemm_kernel <<<(NN + 127) / 128, 256>>>(X, W);
    gather_kernel<<<(NN * 32 + 255) / 256, 256>>>(out);
}

// round 8
// speedup vs baseline: 1.2726x; 1.2726x over previous
#include <cuda_runtime.h>
#include <mma.h>
#include <stdint.h>

using namespace nvcuda;

#define NN   100000
#define INC  1024
#define HIDD 128
#define NE   1600000
#define NB   98          // ceil(NN/1024)
#define NNPAD 100096     // NN rounded up to 128 (GEMM overhang scratch)

// -------- scratch (device globals; no allocations allowed) --------
__device__ float g_hs[(size_t)NNPAD * HIDD];  // h = X @ W (unscaled), padded
__device__ float g_dinv[NN];
__device__ int   g_cnt[NN];
__device__ int   g_start[NN + 1];
__device__ int   g_cursor[NN];
__device__ int   g_srcbuf[NE];
__device__ int   g_bsum[NB];
__device__ int   g_boff[NB];

// ===================== graph-prep kernels =====================
__global__ void init_kernel() {
    int i = blockIdx.x * blockDim.x + threadIdx.x;
    if (i < NN) { g_cnt[i] = 0; g_cursor[i] = 0; }
}

__global__ void count_kernel(const int* __restrict__ ei) {
    int e = blockIdx.x * blockDim.x + threadIdx.x;
    if (e < NE) {
        int c = ei[NE + e];
        if ((unsigned)c < NN) atomicAdd(&g_cnt[c], 1);
    }
}

__global__ void dinv_kernel() {
    int i = blockIdx.x * blockDim.x + threadIdx.x;
    if (i < NN) g_dinv[i] = rsqrtf((float)g_cnt[i] + 1.0f);
}

// ---- decoupled 3-pass scan of g_cnt -> g_start (exclusive, len NN+1) ----
__global__ void blocksum_kernel() {
    __shared__ int ws[32];
    int i = blockIdx.x * 1024 + threadIdx.x;
    int lane = threadIdx.x & 31, wid = threadIdx.x >> 5;
    int v = (i < NN) ? g_cnt[i] : 0;
    #pragma unroll
    for (int off = 16; off > 0; off >>= 1)
        v += __shfl_down_sync(0xffffffff, v, off);
    if (lane == 0) ws[wid] = v;
    __syncthreads();
    if (wid == 0) {
        int s = ws[lane];
        #pragma unroll
        for (int off = 16; off > 0; off >>= 1)
            s += __shfl_down_sync(0xffffffff, s, off);
        if (lane == 0) g_bsum[blockIdx.x] = s;
    }
}

__global__ void bscan_kernel() {   // 1 block, 128 threads over NB=98
    __shared__ int wsum[4];
    int t = threadIdx.x, lane = t & 31, w = t >> 5;
    int v = (t < NB) ? g_bsum[t] : 0;
    int x = v;
    #pragma unroll
    for (int off = 1; off < 32; off <<= 1) {
        int y = __shfl_up_sync(0xffffffff, x, off);
        if (lane >= off) x += y;
    }
    if (lane == 31) wsum[w] = x;
    __syncthreads();
    if (t == 0) {
        int a = 0;
        #pragma unroll
        for (int j = 0; j < 4; j++) { int tmp = wsum[j]; wsum[j] = a; a += tmp; }
    }
    __syncthreads();
    if (t < NB) g_boff[t] = x - v + wsum[w];   // exclusive prefix
}

__global__ void bapply_kernel() {
    __shared__ int ws[32];
    int i = blockIdx.x * 1024 + threadIdx.x;
    int lane = threadIdx.x & 31, wid = threadIdx.x >> 5;
    int v = (i < NN) ? g_cnt[i] : 0;
    int x = v;
    #pragma unroll
    for (int off = 1; off < 32; off <<= 1) {
        int y = __shfl_up_sync(0xffffffff, x, off);
        if (lane >= off) x += y;
    }
    if (lane == 31) ws[wid] = x;
    __syncthreads();
    if (wid == 0) {
        int w = ws[lane];
        #pragma unroll
        for (int off = 1; off < 32; off <<= 1) {
            int y = __shfl_up_sync(0xffffffff, w, off);
            if (lane >= off) w += y;
        }
        ws[lane] = w;
    }
    __syncthreads();
    int incl = x + (wid > 0 ? ws[wid - 1] : 0) + g_boff[blockIdx.x];
    if (i < NN) g_start[i + 1] = incl;
    if (i == 0) g_start[0] = 0;
}

__global__ void fill_kernel(const int* __restrict__ ei) {
    int e = blockIdx.x * blockDim.x + threadIdx.x;
    if (e < NE) {
        int r = ei[e];
        int c = ei[NE + e];
        if ((unsigned)c < NN && (unsigned)r < NN) {
            int pos = atomicAdd(&g_cursor[c], 1);
            g_srcbuf[g_start[c] + pos] = r;
        }
    }
}

// ============== GEMM via WMMA tf32: g_hs = X @ W ==============
// BM=128, BN=128, BK=32, 256 threads (8 warps: 2x4, each warp 64x32).
#define LDA 36     // 32 + 4 pad  (x4B = 144, 16B-aligned rows)
#define LDB 136    // 128 + 8 pad

__global__ __launch_bounds__(256)
void gemm_wmma_kernel(const float* __restrict__ X, const float* __restrict__ W) {
    __shared__ __align__(16) float sA[128 * LDA];  // 18 KB
    __shared__ __align__(16) float sB[32 * LDB];   // 17 KB

    const int tid = threadIdx.x;
    const int wid = tid >> 5;
    const int wr = wid >> 2;          // 0..1  (64-row band)
    const int wc = wid & 3;           // 0..3  (32-col band)
    const int bm = blockIdx.x * 128;

    wmma::fragment<wmma::accumulator, 16, 16, 8, float> acc[4][2];
    #pragma unroll
    for (int i = 0; i < 4; i++)
        #pragma unroll
        for (int j = 0; j < 2; j++)
            wmma::fill_fragment(acc[i][j], 0.0f);

    for (int k0 = 0; k0 < INC; k0 += 32) {
        // A tile: 128 rows x 32 cols -> sA (1024 float4, 4/thread)
        #pragma unroll
        for (int i = 0; i < 4; i++) {
            int id  = tid + i * 256;
            int row = id >> 3;
            int c4  = (id & 7) * 4;
            float4 v = make_float4(0.f, 0.f, 0.f, 0.f);
            if (bm + row < NN)
                v = *(const float4*)(X + (size_t)(bm + row) * INC + k0 + c4);
            *(float4*)(sA + row * LDA + c4) = v;
        }
        // B tile: 32 rows x 128 cols -> sB (1024 float4, 4/thread)
        #pragma unroll
        for (int i = 0; i < 4; i++) {
            int id  = tid + i * 256;
            int row = id >> 5;
            int c4  = (id & 31) * 4;
            *(float4*)(sB + row * LDB + c4) =
                *(const float4*)(W + (size_t)(k0 + row) * HIDD + c4);
        }
        __syncthreads();

        #pragma unroll
        for (int ks = 0; ks < 4; ks++) {
            wmma::fragment<wmma::matrix_a, 16, 16, 8,
                           wmma::precision::tf32, wmma::row_major> af[4];
            wmma::fragment<wmma::matrix_b, 16, 16, 8,
                           wmma::precision::tf32, wmma::row_major> bf[2];
            #pragma unroll
            for (int i = 0; i < 4; i++) {
                wmma::load_matrix_sync(af[i],
                    sA + (wr * 64 + i * 16) * LDA + ks * 8, LDA);
                #pragma unroll
                for (int t = 0; t < af[i].num_elements; t++)
                    af[i].x[t] = wmma::__float_to_tf32(af[i].x[t]);
            }
            #pragma unroll
            for (int j = 0; j < 2; j++) {
                wmma::load_matrix_sync(bf[j],
                    sB + (ks * 8) * LDB + wc * 32 + j * 16, LDB);
                #pragma unroll
                for (int t = 0; t < bf[j].num_elements; t++)
                    bf[j].x[t] = wmma::__float_to_tf32(bf[j].x[t]);
            }
            #pragma unroll
            for (int i = 0; i < 4; i++)
                #pragma unroll
                for (int j = 0; j < 2; j++)
                    wmma::mma_sync(acc[i][j], af[i], bf[j], acc[i][j]);
        }
        __syncthreads();
    }

    // epilogue: store to g_hs (padded -> overhang rows land in scratch)
    #pragma unroll
    for (int i = 0; i < 4; i++) {
        int row = bm + wr * 64 + i * 16;
        #pragma unroll
        for (int j = 0; j < 2; j++) {
            int col = wc * 32 + j * 16;
            wmma::store_matrix_sync(g_hs + (size_t)row * HIDD + col,
                                    acc[i][j], HIDD, wmma::mem_row_major);
        }
    }
}

// -------- gather-reduce: one warp per destination node --------
// out[d] = dinv[d] * ( sum_src h[src]*dinv[src]  +  h[d]*dinv[d] )
__global__ void gather_kernel(float* __restrict__ out) {
    int gw = (blockIdx.x * blockDim.x + threadIdx.x) >> 5;
    int lane = threadIdx.x & 31;
    if (gw >= NN) return;
    const float4* hs4 = (const float4*)g_hs;
    int s0 = g_start[gw], s1 = g_start[gw + 1];
    float dself = g_dinv[gw];
    float4 h = hs4[(size_t)gw * 32 + lane];
    float4 acc = make_float4(h.x * dself, h.y * dself, h.z * dself, h.w * dself);
    for (int j = s0; j < s1; j++) {
        int src = g_srcbuf[j];
        float ds = __ldg(&g_dinv[src]);
        float4 v = hs4[(size_t)src * 32 + lane];
        acc.x = fmaf(v.x, ds, acc.x);
        acc.y = fmaf(v.y, ds, acc.y);
        acc.z = fmaf(v.z, ds, acc.z);
        acc.w = fmaf(v.w, ds, acc.w);
    }
    ((float4*)out)[(size_t)gw * 32 + lane] =
        make_float4(acc.x * dself, acc.y * dself, acc.z * dself, acc.w * dself);
}

extern "C" void kernel_launch(void* const* d_in, const int* in_sizes, int n_in,
                              void* d_out, int out_size) {
    const float* X  = (const float*)d_in[0];
    const float* W  = (const float*)d_in[1];
    const int*   ei = (const int*)d_in[2];
    float* out = (float*)d_out;

    init_kernel     <<<(NN + 255) / 256, 256>>>();
    count_kernel    <<<(NE + 255) / 256, 256>>>(ei);
    dinv_kernel     <<<(NN + 255) / 256, 256>>>();
    blocksum_kernel <<<NB, 1024>>>();
    bscan_kernel    <<<1, 128>>>();
    bapply_kernel   <<<NB, 1024>>>();
    fill_kernel     <<<(NE + 255) / 256, 256>>>(ei);
    gemm_wmma_kernel<<<(NN + 127) / 128, 256>>>(X, W);
    gather_kernel   <<<(NN * 32 + 255) / 256, 256>>>(out);
}

// round 9
// speedup vs baseline: 1.5029x; 1.1809x over previous
#include <cuda_runtime.h>
#include <mma.h>
#include <stdint.h>

using namespace nvcuda;

#define NN   100000
#define INC  1024
#define HIDD 128
#define NE   1600000
#define NB   98          // ceil(NN/1024)
#define NNPAD 100096     // NN rounded up to 128 (GEMM overhang scratch)

// -------- scratch (device globals; no allocations allowed) --------
__device__ float g_hs[(size_t)NNPAD * HIDD];  // h = X @ W (unscaled), padded
__device__ float g_dinv[NN];
__device__ int   g_cnt[NN];
__device__ int   g_start[NN + 1];
__device__ int   g_cursor[NN];
__device__ int   g_srcbuf[NE];
__device__ int   g_bsum[NB];
__device__ int   g_boff[NB];

// ===================== graph-prep kernels =====================
__global__ void init_kernel() {
    int i = blockIdx.x * blockDim.x + threadIdx.x;
    if (i < NN) { g_cnt[i] = 0; g_cursor[i] = 0; }
}

__global__ void count_kernel(const int* __restrict__ ei) {
    int e = blockIdx.x * blockDim.x + threadIdx.x;
    if (e < NE) {
        int c = ei[NE + e];
        if ((unsigned)c < NN) atomicAdd(&g_cnt[c], 1);
    }
}

__global__ void dinv_kernel() {
    int i = blockIdx.x * blockDim.x + threadIdx.x;
    if (i < NN) g_dinv[i] = rsqrtf((float)g_cnt[i] + 1.0f);
}

// ---- decoupled 3-pass scan of g_cnt -> g_start (exclusive, len NN+1) ----
__global__ void blocksum_kernel() {
    __shared__ int ws[32];
    int i = blockIdx.x * 1024 + threadIdx.x;
    int lane = threadIdx.x & 31, wid = threadIdx.x >> 5;
    int v = (i < NN) ? g_cnt[i] : 0;
    #pragma unroll
    for (int off = 16; off > 0; off >>= 1)
        v += __shfl_down_sync(0xffffffff, v, off);
    if (lane == 0) ws[wid] = v;
    __syncthreads();
    if (wid == 0) {
        int s = ws[lane];
        #pragma unroll
        for (int off = 16; off > 0; off >>= 1)
            s += __shfl_down_sync(0xffffffff, s, off);
        if (lane == 0) g_bsum[blockIdx.x] = s;
    }
}

__global__ void bscan_kernel() {   // 1 block, 128 threads over NB=98
    __shared__ int wsum[4];
    int t = threadIdx.x, lane = t & 31, w = t >> 5;
    int v = (t < NB) ? g_bsum[t] : 0;
    int x = v;
    #pragma unroll
    for (int off = 1; off < 32; off <<= 1) {
        int y = __shfl_up_sync(0xffffffff, x, off);
        if (lane >= off) x += y;
    }
    if (lane == 31) wsum[w] = x;
    __syncthreads();
    if (t == 0) {
        int a = 0;
        #pragma unroll
        for (int j = 0; j < 4; j++) { int tmp = wsum[j]; wsum[j] = a; a += tmp; }
    }
    __syncthreads();
    if (t < NB) g_boff[t] = x - v + wsum[w];   // exclusive prefix
}

__global__ void bapply_kernel() {
    __shared__ int ws[32];
    int i = blockIdx.x * 1024 + threadIdx.x;
    int lane = threadIdx.x & 31, wid = threadIdx.x >> 5;
    int v = (i < NN) ? g_cnt[i] : 0;
    int x = v;
    #pragma unroll
    for (int off = 1; off < 32; off <<= 1) {
        int y = __shfl_up_sync(0xffffffff, x, off);
        if (lane >= off) x += y;
    }
    if (lane == 31) ws[wid] = x;
    __syncthreads();
    if (wid == 0) {
        int w = ws[lane];
        #pragma unroll
        for (int off = 1; off < 32; off <<= 1) {
            int y = __shfl_up_sync(0xffffffff, w, off);
            if (lane >= off) w += y;
        }
        ws[lane] = w;
    }
    __syncthreads();
    int incl = x + (wid > 0 ? ws[wid - 1] : 0) + g_boff[blockIdx.x];
    if (i < NN) g_start[i + 1] = incl;
    if (i == 0) g_start[0] = 0;
}

__global__ void fill_kernel(const int* __restrict__ ei) {
    int e = blockIdx.x * blockDim.x + threadIdx.x;
    if (e < NE) {
        int r = ei[e];
        int c = ei[NE + e];
        if ((unsigned)c < NN && (unsigned)r < NN) {
            int pos = atomicAdd(&g_cursor[c], 1);
            g_srcbuf[g_start[c] + pos] = r;
        }
    }
}

// ============== GEMM via WMMA tf32 + cp.async 2-stage pipeline ==============
// BM=128, BN=128, BK=32, 256 threads (8 warps: 2x4, each warp 64x32).
#define LDA 36     // 32 + 4 pad
#define LDB 136    // 128 + 8 pad
#define ASZ (128 * LDA)
#define BSZ (32 * LDB)
#define NC  (INC / 32)   // 32 K-chunks
#define GEMM_SMEM ((2 * ASZ + 2 * BSZ) * 4)   // 71680 bytes

__device__ __forceinline__ uint32_t smem_u32(const void* p) {
    uint32_t a;
    asm("{ .reg .u64 t; cvta.to.shared.u64 t, %1; cvt.u32.u64 %0, t; }"
        : "=r"(a) : "l"(p));
    return a;
}
__device__ __forceinline__ void cp_async16(uint32_t dst, const void* src, int src_bytes) {
    asm volatile("cp.async.cg.shared.global [%0], [%1], 16, %2;"
                 :: "r"(dst), "l"(src), "r"(src_bytes));
}
#define CP_COMMIT() asm volatile("cp.async.commit_group;" ::: "memory")
#define CP_WAIT(N)  asm volatile("cp.async.wait_group %0;" :: "n"(N) : "memory")

__global__ __launch_bounds__(256)
void gemm_wmma_kernel(const float* __restrict__ X, const float* __restrict__ W) {
    extern __shared__ __align__(16) float smem[];
    float* sA[2] = { smem, smem + ASZ };
    float* sB[2] = { smem + 2 * ASZ, smem + 2 * ASZ + BSZ };

    const int tid = threadIdx.x;
    const int wid = tid >> 5;
    const int wr = wid >> 2;          // 0..1  (64-row band)
    const int wc = wid & 3;           // 0..3  (32-col band)
    const int bm = blockIdx.x * 128;

    // per-thread staging coords (constant across chunks)
    const int arow = tid >> 3,  ac4 = (tid & 7) * 4;    // +32 rows per i
    const int brow = tid >> 5,  bc4 = (tid & 31) * 4;   // +8  rows per i
    uint32_t aAbase[2] = { smem_u32(sA[0]), smem_u32(sA[1]) };
    uint32_t aBbase[2] = { smem_u32(sB[0]), smem_u32(sB[1]) };

    wmma::fragment<wmma::accumulator, 16, 16, 8, float> acc[4][2];
    #pragma unroll
    for (int i = 0; i < 4; i++)
        #pragma unroll
        for (int j = 0; j < 2; j++)
            wmma::fill_fragment(acc[i][j], 0.0f);

    auto prefetch = [&](int st, int k0) {
        #pragma unroll
        for (int i = 0; i < 4; i++) {
            int row = arow + i * 32;
            int ok = (bm + row < NN) ? 16 : 0;
            cp_async16(aAbase[st] + (uint32_t)(row * LDA + ac4) * 4,
                       X + (size_t)(bm + row) * INC + k0 + ac4, ok);
        }
        #pragma unroll
        for (int i = 0; i < 4; i++) {
            int row = brow + i * 8;
            cp_async16(aBbase[st] + (uint32_t)(row * LDB + bc4) * 4,
                       W + (size_t)(k0 + row) * HIDD + bc4, 16);
        }
    };

    prefetch(0, 0);
    CP_COMMIT();

    for (int c = 0; c < NC; c++) {
        int st = c & 1;
        if (c + 1 < NC) {
            prefetch(st ^ 1, (c + 1) * 32);
            CP_COMMIT();
            CP_WAIT(1);            // stage c resident
        } else {
            CP_WAIT(0);
        }
        __syncthreads();

        const float* cA = sA[st];
        const float* cB = sB[st];
        #pragma unroll
        for (int ks = 0; ks < 4; ks++) {
            wmma::fragment<wmma::matrix_a, 16, 16, 8,
                           wmma::precision::tf32, wmma::row_major> af[4];
            wmma::fragment<wmma::matrix_b, 16, 16, 8,
                           wmma::precision::tf32, wmma::row_major> bf[2];
            #pragma unroll
            for (int i = 0; i < 4; i++) {
                wmma::load_matrix_sync(af[i],
                    cA + (wr * 64 + i * 16) * LDA + ks * 8, LDA);
                #pragma unroll
                for (int t = 0; t < af[i].num_elements; t++)
                    af[i].x[t] = wmma::__float_to_tf32(af[i].x[t]);
            }
            #pragma unroll
            for (int j = 0; j < 2; j++) {
                wmma::load_matrix_sync(bf[j],
                    cB + (ks * 8) * LDB + wc * 32 + j * 16, LDB);
                #pragma unroll
                for (int t = 0; t < bf[j].num_elements; t++)
                    bf[j].x[t] = wmma::__float_to_tf32(bf[j].x[t]);
            }
            #pragma unroll
            for (int i = 0; i < 4; i++)
                #pragma unroll
                for (int j = 0; j < 2; j++)
                    wmma::mma_sync(acc[i][j], af[i], bf[j], acc[i][j]);
        }
        __syncthreads();   // all warps done with stage st before it is refilled
    }

    // epilogue: store to g_hs (padded -> overhang rows land in scratch)
    #pragma unroll
    for (int i = 0; i < 4; i++) {
        int row = bm + wr * 64 + i * 16;
        #pragma unroll
        for (int j = 0; j < 2; j++) {
            int col = wc * 32 + j * 16;
            wmma::store_matrix_sync(g_hs + (size_t)row * HIDD + col,
                                    acc[i][j], HIDD, wmma::mem_row_major);
        }
    }
}

// -------- gather-reduce: one warp per destination node --------
// out[d] = dinv[d] * ( sum_src h[src]*dinv[src]  +  h[d]*dinv[d] )
__global__ void gather_kernel(float* __restrict__ out) {
    int gw = (blockIdx.x * blockDim.x + threadIdx.x) >> 5;
    int lane = threadIdx.x & 31;
    if (gw >= NN) return;
    const float4* hs4 = (const float4*)g_hs;
    int s0 = g_start[gw], s1 = g_start[gw + 1];
    float dself = g_dinv[gw];
    float4 h = hs4[(size_t)gw * 32 + lane];
    float4 acc = make_float4(h.x * dself, h.y * dself, h.z * dself, h.w * dself);
    for (int j = s0; j < s1; j++) {
        int src = g_srcbuf[j];
        float ds = __ldg(&g_dinv[src]);
        float4 v = hs4[(size_t)src * 32 + lane];
        acc.x = fmaf(v.x, ds, acc.x);
        acc.y = fmaf(v.y, ds, acc.y);
        acc.z = fmaf(v.z, ds, acc.z);
        acc.w = fmaf(v.w, ds, acc.w);
    }
    ((float4*)out)[(size_t)gw * 32 + lane] =
        make_float4(acc.x * dself, acc.y * dself, acc.z * dself, acc.w * dself);
}

extern "C" void kernel_launch(void* const* d_in, const int* in_sizes, int n_in,
                              void* d_out, int out_size) {
    const float* X  = (const float*)d_in[0];
    const float* W  = (const float*)d_in[1];
    const int*   ei = (const int*)d_in[2];
    float* out = (float*)d_out;

    cudaFuncSetAttribute(gemm_wmma_kernel,
                         cudaFuncAttributeMaxDynamicSharedMemorySize, GEMM_SMEM);

    init_kernel     <<<(NN + 255) / 256, 256>>>();
    count_kernel    <<<(NE + 255) / 256, 256>>>(ei);
    dinv_kernel     <<<(NN + 255) / 256, 256>>>();
    blocksum_kernel <<<NB, 1024>>>();
    bscan_kernel    <<<1, 128>>>();
    bapply_kernel   <<<NB, 1024>>>();
    fill_kernel     <<<(NE + 255) / 256, 256>>>(ei);
    gemm_wmma_kernel<<<(NN + 127) / 128, 256, GEMM_SMEM>>>(X, W);
    gather_kernel   <<<(NN * 32 + 255) / 256, 256>>>(out);
}